// round 15
// baseline (speedup 1.0000x reference)
#include <cuda_runtime.h>
#include <cuda_fp16.h>

#define DDIM    256
#define NMAX    8192
#define LISTCAP 768     // mean nnz ~164, sd ~12.7; cnt+8 pad always fits
#define BW      4       // per-warp batch in gat

// Scratch: NORMALIZED y rows in fp16 (4 MB, L2-resident) + norms (fp32)
// + per-row neighbor lists + release/acquire flag (g_cnt, -1 = not ready).
__device__ __half2        g_yn16[(size_t)NMAX * (DDIM / 2)];
__device__ float          g_ynorm[NMAX];
__device__ unsigned short g_list[(size_t)NMAX * LISTCAP];
__device__ int            g_cnt[NMAX];

// exp(d - 1), d = qi * 2^-22:  exp2(qi*(log2e/2^22) - log2e)
#define EXP_C1 3.440142822265625e-07f
#define EXP_C2 1.4426950408889634f

__device__ __forceinline__ float warp_sum(float v) {
#pragma unroll
    for (int off = 16; off; off >>= 1)
        v += __shfl_xor_sync(0xffffffffu, v, off);
    return v;
}

__device__ __forceinline__ int redux_add_s32(int v) {
    int r;
    asm("redux.sync.add.s32 %0, %1, 0xffffffff;" : "=r"(r) : "r"(v));
    return r;
}

__device__ __forceinline__ float ex2_approx(float t) {
    float r;
    asm("ex2.approx.f32 %0, %1;" : "=f"(r) : "f"(t));
    return r;
}

// Kernel 1: reset flags to -1 (replay-safe) + prep all y rows (one warp each).
__global__ void __launch_bounds__(256) prep_reset(const float* __restrict__ y,
                                                  int N, int M) {
    int gtid = blockIdx.x * 256 + threadIdx.x;
    if (gtid < N) g_cnt[gtid] = -1;

    int w    = gtid >> 5;
    int lane = threadIdx.x & 31;
    if (w >= M) return;

    const float4* yp = (const float4*)(y + (size_t)w * DDIM);
    float4 a = yp[lane * 2];
    float4 b = yp[lane * 2 + 1];
    float ss = a.x * a.x + a.y * a.y + a.z * a.z + a.w * a.w
             + b.x * b.x + b.y * b.y + b.z * b.z + b.w * b.w;
    ss = warp_sum(ss);
    float n   = fmaxf(sqrtf(ss), 1e-8f);   // matches max(norm, EPS)
    float inv = 1.0f / n;
    if (lane == 0) g_ynorm[w] = n;

    __half2* o = g_yn16 + (size_t)w * (DDIM / 2) + lane * 4;
    o[0] = __floats2half2_rn(a.x * inv, a.y * inv);
    o[1] = __floats2half2_rn(a.z * inv, a.w * inv);
    o[2] = __floats2half2_rn(b.x * inv, b.y * inv);
    o[3] = __floats2half2_rn(b.z * inv, b.w * inv);
}

// Kernel 2: interleaved scan/gat CTAs for overlap.
//   even bid -> scan row bid/2 (DRAM-streaming, issue-light)
//   odd  bid -> gat  row bid/2 (issue-bound, DRAM-idle), waits on its row's
//              flag via acquire spin. Disjoint rooflines share each SM.
__global__ void __launch_bounds__(256) fused(const float* __restrict__ adj,
                                             const float* __restrict__ x,
                                             float* __restrict__ out,
                                             int N, int M) {
    __shared__ int s_cnt;
    __shared__ alignas(8) unsigned short s_list[LISTCAP];
    __shared__ float s_o[8][DDIM];
    __shared__ float s_l[8];

    const int bid  = blockIdx.x;
    const int row  = bid >> 1;
    const int tid  = threadIdx.x;
    const int wib  = tid >> 5;
    const int lane = tid & 31;

    if ((bid & 1) == 0) {
        // ================= SCAN CTA =================
        if (tid == 0) s_cnt = 0;
        __syncthreads();

        const float* arow = adj + (size_t)row * M;
        unsigned short* lst = g_list + (size_t)row * LISTCAP;
        const unsigned lt = (1u << lane) - 1u;

        for (int seg = wib * 1024; seg < M; seg += 8 * 1024) {
            float4 a[8];
#pragma unroll
            for (int u = 0; u < 8; ++u)
                a[u] = __ldcs((const float4*)(arow + seg + u * 128 + lane * 4));

#pragma unroll
            for (int u = 0; u < 8; ++u) {
                int jb = seg + u * 128 + lane * 4;
                unsigned m0 = __ballot_sync(0xffffffffu, a[u].x != 0.f);
                unsigned m1 = __ballot_sync(0xffffffffu, a[u].y != 0.f);
                unsigned m2 = __ballot_sync(0xffffffffu, a[u].z != 0.f);
                unsigned m3 = __ballot_sync(0xffffffffu, a[u].w != 0.f);
                int c0 = __popc(m0), c1 = __popc(m1), c2 = __popc(m2), c3 = __popc(m3);
                int tot = c0 + c1 + c2 + c3;
                int base = 0;
                if (tot) {
                    if (lane == 0) base = atomicAdd(&s_cnt, tot);
                    base = __shfl_sync(0xffffffffu, base, 0);
                    if (a[u].x != 0.f) lst[base + __popc(m0 & lt)]                = (unsigned short)(jb);
                    if (a[u].y != 0.f) lst[base + c0 + __popc(m1 & lt)]           = (unsigned short)(jb + 1);
                    if (a[u].z != 0.f) lst[base + c0 + c1 + __popc(m2 & lt)]      = (unsigned short)(jb + 2);
                    if (a[u].w != 0.f) lst[base + c0 + c1 + c2 + __popc(m3 & lt)] = (unsigned short)(jb + 3);
                }
            }
        }
        __syncthreads();
        // Publish: all lst writes (all threads) are ordered before this
        // release store via bar.sync causality (PTX message-passing pattern).
        if (tid == 0) {
            int c = s_cnt;
            asm volatile("st.release.gpu.global.s32 [%0], %1;"
                         :: "l"(&g_cnt[row]), "r"(c) : "memory");
        }
    } else {
        // ================= GAT CTA =================
        // Acquire-spin on this row's flag (backoff keeps issue cost tiny).
        if (tid == 0) {
            int c;
            while (true) {
                asm volatile("ld.acquire.gpu.global.s32 %0, [%1];"
                             : "=r"(c) : "l"(&g_cnt[row]) : "memory");
                if (c >= 0) break;
                __nanosleep(256);
            }
            s_cnt = c;
        }
        __syncthreads();
        const int cnt = s_cnt;

        // Stage neighbor list + zero pad (for ushort4 reads).
        const unsigned short* glst = g_list + (size_t)row * LISTCAP;
        for (int t = tid; t < cnt; t += 256)
            s_list[t] = glst[t];
        if (tid < 8) s_list[cnt + tid] = 0;

        // Per-warp: load + normalize x row (lane owns dims [8l, 8l+8)).
        const float4* xp = (const float4*)(x + (size_t)row * DDIM);
        float4 xa = xp[lane * 2];
        float4 xb = xp[lane * 2 + 1];
        float ss = xa.x * xa.x + xa.y * xa.y + xa.z * xa.z + xa.w * xa.w
                 + xb.x * xb.x + xb.y * xb.y + xb.z * xb.z + xb.w * xb.w;
        ss = warp_sum(ss);
        float xinv = 1.0f / fmaxf(sqrtf(ss), 1e-8f);

        __half2 xh0 = __floats2half2_rn(xa.x * xinv, xa.y * xinv);
        __half2 xh1 = __floats2half2_rn(xa.z * xinv, xa.w * xinv);
        __half2 xh2 = __floats2half2_rn(xb.x * xinv, xb.y * xinv);
        __half2 xh3 = __floats2half2_rn(xb.z * xinv, xb.w * xinv);

        __syncthreads();   // list staged

        __half2 oh0 = __float2half2_rn(0.f);
        __half2 oh1 = oh0, oh2 = oh0, oh3 = oh0;
        float l = 0.f;

        for (int base = wib * BW; base < cnt; base += 8 * BW) {
            ushort4 pj = *(const ushort4*)(s_list + base);
            int jj[BW] = { pj.x, pj.y, pj.z, pj.w };

            uint4 v[BW];
#pragma unroll
            for (int k = 0; k < BW; ++k)
                v[k] = *(const uint4*)(g_yn16 + (size_t)jj[k] * (DDIM / 2) + lane * 4);

            float yn[BW];
#pragma unroll
            for (int k = 0; k < BW; ++k)
                yn[k] = __ldg(&g_ynorm[jj[k]]);

#pragma unroll
            for (int k = 0; k < BW; ++k) {
                __half2 a = __hmul2(xh0, *(const __half2*)&v[k].x);
                a = __hfma2(xh1, *(const __half2*)&v[k].y, a);
                a = __hfma2(xh2, *(const __half2*)&v[k].z, a);
                a = __hfma2(xh3, *(const __half2*)&v[k].w, a);
                float2 cf = __half22float2(a);
                int qi = __float2int_rn((cf.x + cf.y) * 4194304.0f);
                qi = redux_add_s32(qi);
                float e = ex2_approx(fmaf((float)qi, EXP_C1, -EXP_C2));
                float p = (base + k < cnt) ? e : 0.f;
                l += p;
                __half2 ph = __float2half2_rn(p * yn[k]);
                oh0 = __hfma2(ph, *(const __half2*)&v[k].x, oh0);
                oh1 = __hfma2(ph, *(const __half2*)&v[k].y, oh1);
                oh2 = __hfma2(ph, *(const __half2*)&v[k].z, oh2);
                oh3 = __hfma2(ph, *(const __half2*)&v[k].w, oh3);
            }
        }

        // Cross-warp combine.
        float2 f0 = __half22float2(oh0);
        float2 f1 = __half22float2(oh1);
        float2 f2 = __half22float2(oh2);
        float2 f3 = __half22float2(oh3);
        float* so = s_o[wib] + lane * 8;
        so[0] = f0.x; so[1] = f0.y; so[2] = f1.x; so[3] = f1.y;
        so[4] = f2.x; so[5] = f2.y; so[6] = f3.x; so[7] = f3.y;
        if (lane == 0) s_l[wib] = l;
        __syncthreads();

        float ltot = s_l[0] + s_l[1] + s_l[2] + s_l[3]
                   + s_l[4] + s_l[5] + s_l[6] + s_l[7];
        float acc = 0.f;
#pragma unroll
        for (int w = 0; w < 8; ++w)
            acc += s_o[w][tid];

        float xv = __ldg(x + (size_t)row * DDIM + tid);
        out[(size_t)row * DDIM + tid] = fmaf(0.5f / ltot, acc, 0.5f * xv);
    }
}

extern "C" void kernel_launch(void* const* d_in, const int* in_sizes, int n_in,
                              void* d_out, int out_size) {
    const float* x   = (const float*)d_in[0];
    const float* y   = (const float*)d_in[1];
    const float* adj = (const float*)d_in[2];
    float* out       = (float*)d_out;

    int N = in_sizes[0] / DDIM;   // 8192
    int M = in_sizes[1] / DDIM;   // 8192

    int prep_blocks = (M * 32 + 255) / 256;
    prep_reset<<<prep_blocks, 256>>>(y, N, M);

    fused<<<2 * N, 256>>>(adj, x, out, N, M);
}

// round 16
// speedup vs baseline: 1.3750x; 1.3750x over previous
#include <cuda_runtime.h>
#include <cuda_fp16.h>

#define DDIM    256
#define NMAX    8192
#define LISTCAP 768     // mean nnz ~164, sd ~12.7; cnt+8 pad always fits
#define BW      4       // per-warp batch in gat_main

// Scratch: NORMALIZED y rows in fp16 (4 MB, L2-resident) + norms (fp32)
// + CSR-style neighbor lists built by csr_scan.
__device__ __half2        g_yn16[(size_t)NMAX * (DDIM / 2)];
__device__ float          g_ynorm[NMAX];
__device__ unsigned short g_list[(size_t)NMAX * LISTCAP];
__device__ int            g_cnt[NMAX];

// exp(d - 1), d = qi * 2^-22:  exp2(qi*(log2e/2^22) - log2e)
#define EXP_C1 3.440142822265625e-07f
#define EXP_C2 1.4426950408889634f

__device__ __forceinline__ float warp_sum(float v) {
#pragma unroll
    for (int off = 16; off; off >>= 1)
        v += __shfl_xor_sync(0xffffffffu, v, off);
    return v;
}

// Single-instruction integer warp reduction; sum lands in ALL lanes.
__device__ __forceinline__ int redux_add_s32(int v) {
    int r;
    asm("redux.sync.add.s32 %0, %1, 0xffffffff;" : "=r"(r) : "r"(v));
    return r;
}

__device__ __forceinline__ float ex2_approx(float t) {
    float r;
    asm("ex2.approx.f32 %0, %1;" : "=f"(r) : "f"(t));
    return r;
}

// Streaming pass: one CTA per adj row. 8 warps scan disjoint 1024-col
// segments (8 float4 loads in flight), ballot-compact nonzero indices.
// Warp 0 additionally preps y row `row`. Tail zero-padded.
__global__ void __launch_bounds__(256) csr_scan(const float* __restrict__ adj,
                                                const float* __restrict__ y,
                                                int M) {
    __shared__ int s_cnt;
    const int row  = blockIdx.x;
    const int tid  = threadIdx.x;
    const int wib  = tid >> 5;
    const int lane = tid & 31;

    if (tid == 0) s_cnt = 0;
    __syncthreads();

    // ---- warp 0: prep y row (independent of scan) ----
    if (wib == 0 && row < M) {
        const float4* yp = (const float4*)(y + (size_t)row * DDIM);
        float4 a = yp[lane * 2];
        float4 b = yp[lane * 2 + 1];
        float ss = a.x * a.x + a.y * a.y + a.z * a.z + a.w * a.w
                 + b.x * b.x + b.y * b.y + b.z * b.z + b.w * b.w;
        ss = warp_sum(ss);
        float n   = fmaxf(sqrtf(ss), 1e-8f);
        float inv = 1.0f / n;
        if (lane == 0) g_ynorm[row] = n;
        __half2* o = g_yn16 + (size_t)row * (DDIM / 2) + lane * 4;
        o[0] = __floats2half2_rn(a.x * inv, a.y * inv);
        o[1] = __floats2half2_rn(a.z * inv, a.w * inv);
        o[2] = __floats2half2_rn(b.x * inv, b.y * inv);
        o[3] = __floats2half2_rn(b.z * inv, b.w * inv);
    }

    const float* arow = adj + (size_t)row * M;
    unsigned short* lst = g_list + (size_t)row * LISTCAP;
    const unsigned lt = (1u << lane) - 1u;

    for (int seg = wib * 1024; seg < M; seg += 8 * 1024) {
        float4 a[8];
#pragma unroll
        for (int u = 0; u < 8; ++u)
            a[u] = __ldcs((const float4*)(arow + seg + u * 128 + lane * 4));

#pragma unroll
        for (int u = 0; u < 8; ++u) {
            int jb = seg + u * 128 + lane * 4;
            unsigned m0 = __ballot_sync(0xffffffffu, a[u].x != 0.f);
            unsigned m1 = __ballot_sync(0xffffffffu, a[u].y != 0.f);
            unsigned m2 = __ballot_sync(0xffffffffu, a[u].z != 0.f);
            unsigned m3 = __ballot_sync(0xffffffffu, a[u].w != 0.f);
            int c0 = __popc(m0), c1 = __popc(m1), c2 = __popc(m2), c3 = __popc(m3);
            int tot = c0 + c1 + c2 + c3;
            int base = 0;
            if (tot) {
                if (lane == 0) base = atomicAdd(&s_cnt, tot);
                base = __shfl_sync(0xffffffffu, base, 0);
                if (a[u].x != 0.f) lst[base + __popc(m0 & lt)]                = (unsigned short)(jb);
                if (a[u].y != 0.f) lst[base + c0 + __popc(m1 & lt)]           = (unsigned short)(jb + 1);
                if (a[u].z != 0.f) lst[base + c0 + c1 + __popc(m2 & lt)]      = (unsigned short)(jb + 2);
                if (a[u].w != 0.f) lst[base + c0 + c1 + c2 + __popc(m3 & lt)] = (unsigned short)(jb + 3);
            }
        }
    }
    __syncthreads();
    if (tid == 0) g_cnt[row] = s_cnt;
    if (tid < 8) lst[s_cnt + tid] = 0;   // pad
}

// One CTA (256 threads, 8 warps) per output row.
// Full batches run an unpredicated fast path; only the final partial batch
// takes the predicated path. Fused ex2 softmax, REDUX reduction, fp16 P@y.
__global__ void __launch_bounds__(256) gat_main(const float* __restrict__ x,
                                                float* __restrict__ out,
                                                int N, int M) {
    __shared__ alignas(8) unsigned short s_list[LISTCAP];
    __shared__ float s_o[8][DDIM];
    __shared__ float s_l[8];

    const int i    = blockIdx.x;
    const int tid  = threadIdx.x;
    const int wib  = tid >> 5;
    const int lane = tid & 31;

    // ---- Stage neighbor list (padded by csr_scan) ----
    const int cnt = g_cnt[i];
    const unsigned short* glst = g_list + (size_t)i * LISTCAP;
    for (int t = tid; t < cnt; t += 256)
        s_list[t] = glst[t];
    if (tid < 8) s_list[cnt + tid] = 0;

    // ---- Per-warp: load + normalize x row (lane owns dims [8l, 8l+8)) ----
    const float4* xp = (const float4*)(x + (size_t)i * DDIM);
    float4 xa = xp[lane * 2];
    float4 xb = xp[lane * 2 + 1];
    float ss = xa.x * xa.x + xa.y * xa.y + xa.z * xa.z + xa.w * xa.w
             + xb.x * xb.x + xb.y * xb.y + xb.z * xb.z + xb.w * xb.w;
    ss = warp_sum(ss);
    float xinv = 1.0f / fmaxf(sqrtf(ss), 1e-8f);

    __half2 xh0 = __floats2half2_rn(xa.x * xinv, xa.y * xinv);
    __half2 xh1 = __floats2half2_rn(xa.z * xinv, xa.w * xinv);
    __half2 xh2 = __floats2half2_rn(xb.x * xinv, xb.y * xinv);
    __half2 xh3 = __floats2half2_rn(xb.z * xinv, xb.w * xinv);

    __syncthreads();   // list staged

    // ---- Batched neighbor processing (fp16 accumulation, ~21/warp) ----
    __half2 oh0 = __float2half2_rn(0.f);
    __half2 oh1 = oh0, oh2 = oh0, oh3 = oh0;
    float l = 0.f;

    for (int base = wib * BW; base < cnt; base += 8 * BW) {
        // One LDS.64 fetches all 4 indices (tail zero-padded, safe).
        ushort4 pj = *(const ushort4*)(s_list + base);
        int jj[BW] = { pj.x, pj.y, pj.z, pj.w };

        uint4 v[BW];
#pragma unroll
        for (int k = 0; k < BW; ++k)
            v[k] = *(const uint4*)(g_yn16 + (size_t)jj[k] * (DDIM / 2) + lane * 4);

        float yn[BW];
#pragma unroll
        for (int k = 0; k < BW; ++k)
            yn[k] = __ldg(&g_ynorm[jj[k]]);

        if (base + BW <= cnt) {
            // -------- full batch: no predication --------
#pragma unroll
            for (int k = 0; k < BW; ++k) {
                __half2 a = __hmul2(xh0, *(const __half2*)&v[k].x);
                a = __hfma2(xh1, *(const __half2*)&v[k].y, a);
                a = __hfma2(xh2, *(const __half2*)&v[k].z, a);
                a = __hfma2(xh3, *(const __half2*)&v[k].w, a);
                float2 cf = __half22float2(a);
                int qi = __float2int_rn((cf.x + cf.y) * 4194304.0f);
                qi = redux_add_s32(qi);
                float e = ex2_approx(fmaf((float)qi, EXP_C1, -EXP_C2));
                l += e;
                __half2 ph = __float2half2_rn(e * yn[k]);
                oh0 = __hfma2(ph, *(const __half2*)&v[k].x, oh0);
                oh1 = __hfma2(ph, *(const __half2*)&v[k].y, oh1);
                oh2 = __hfma2(ph, *(const __half2*)&v[k].z, oh2);
                oh3 = __hfma2(ph, *(const __half2*)&v[k].w, oh3);
            }
        } else {
            // -------- final partial batch: predicated --------
#pragma unroll
            for (int k = 0; k < BW; ++k) {
                __half2 a = __hmul2(xh0, *(const __half2*)&v[k].x);
                a = __hfma2(xh1, *(const __half2*)&v[k].y, a);
                a = __hfma2(xh2, *(const __half2*)&v[k].z, a);
                a = __hfma2(xh3, *(const __half2*)&v[k].w, a);
                float2 cf = __half22float2(a);
                int qi = __float2int_rn((cf.x + cf.y) * 4194304.0f);
                qi = redux_add_s32(qi);
                float e = ex2_approx(fmaf((float)qi, EXP_C1, -EXP_C2));
                float p = (base + k < cnt) ? e : 0.f;
                l += p;
                __half2 ph = __float2half2_rn(p * yn[k]);
                oh0 = __hfma2(ph, *(const __half2*)&v[k].x, oh0);
                oh1 = __hfma2(ph, *(const __half2*)&v[k].y, oh1);
                oh2 = __hfma2(ph, *(const __half2*)&v[k].z, oh2);
                oh3 = __hfma2(ph, *(const __half2*)&v[k].w, oh3);
            }
        }
    }

    // ---- Cross-warp combine (convert fp16 accumulators once per warp) ----
    float2 f0 = __half22float2(oh0);
    float2 f1 = __half22float2(oh1);
    float2 f2 = __half22float2(oh2);
    float2 f3 = __half22float2(oh3);
    float* so = s_o[wib] + lane * 8;
    so[0] = f0.x; so[1] = f0.y; so[2] = f1.x; so[3] = f1.y;
    so[4] = f2.x; so[5] = f2.y; so[6] = f3.x; so[7] = f3.y;
    if (lane == 0) s_l[wib] = l;
    __syncthreads();

    // thread tid owns dim tid
    float ltot = s_l[0] + s_l[1] + s_l[2] + s_l[3]
               + s_l[4] + s_l[5] + s_l[6] + s_l[7];
    float acc = 0.f;
#pragma unroll
    for (int w = 0; w < 8; ++w)
        acc += s_o[w][tid];

    float xv = __ldg(x + (size_t)i * DDIM + tid);   // L1/L2 hit (row just read)
    out[(size_t)i * DDIM + tid] = fmaf(0.5f / ltot, acc, 0.5f * xv);
}

extern "C" void kernel_launch(void* const* d_in, const int* in_sizes, int n_in,
                              void* d_out, int out_size) {
    const float* x   = (const float*)d_in[0];
    const float* y   = (const float*)d_in[1];
    const float* adj = (const float*)d_in[2];
    float* out       = (float*)d_out;

    int N = in_sizes[0] / DDIM;   // 8192
    int M = in_sizes[1] / DDIM;   // 8192

    csr_scan<<<N, 256>>>(adj, y, M);

    gat_main<<<N, 256>>>(x, out, N, M);
}